// round 5
// baseline (speedup 1.0000x reference)
#include <cuda_runtime.h>
#include <cstdint>
#include <cstddef>

// ---------------- problem constants ----------------
#define HEADS   32
#define HDIM    64      // P
#define NSTATE  32
#define KCONV   4
#define DMODEL  2048
#define CONVDIM 2112
#define PROJW   4192
#define BATCH   4
#define LSEQ    2048
#define BL      (BATCH * LSEQ)   // 8192
#define PROJPAD 4352             // 17 * 256 (padded N for GEMM1 B operand)

// ---------------- scratch (device globals; no runtime alloc) ----------------
__device__ float g_proj[(size_t)BL * PROJW];       // 137 MB
__device__ float g_conv[(size_t)BL * CONVDIM];     // 69 MB
__device__ float g_dt  [(size_t)BATCH * HEADS * LSEQ];
__device__ float g_dA  [(size_t)BATCH * HEADS * LSEQ];
__device__ float g_y   [(size_t)BL * DMODEL];      // 67 MB (tf32-rounded by rmsnorm)
__device__ float g_xa  [(size_t)BL * DMODEL];      // tf32-rounded x
__device__ float g_wa  [(size_t)PROJPAD * DMODEL]; // tf32-rounded W_in^T, padded rows
__device__ float g_wb  [(size_t)DMODEL * DMODEL];  // tf32-rounded W_out^T

// ---------------- packed fp32x2 helpers ----------------
__device__ __forceinline__ unsigned long long pack2(float lo, float hi) {
    unsigned long long r;
    asm("mov.b64 %0, {%1, %2};" : "=l"(r) : "f"(lo), "f"(hi));
    return r;
}
__device__ __forceinline__ unsigned long long mul2(unsigned long long a, unsigned long long b) {
    unsigned long long r;
    asm("mul.rn.f32x2 %0, %1, %2;" : "=l"(r) : "l"(a), "l"(b));
    return r;
}
__device__ __forceinline__ unsigned long long fma2v(unsigned long long a, unsigned long long b,
                                                    unsigned long long c) {
    unsigned long long r;
    asm("fma.rn.f32x2 %0, %1, %2, %3;" : "=l"(r) : "l"(a), "l"(b), "l"(c));
    return r;
}
__device__ __forceinline__ unsigned long long add2(unsigned long long a, unsigned long long b) {
    unsigned long long r;
    asm("add.rn.f32x2 %0, %1, %2;" : "=l"(r) : "l"(a), "l"(b));
    return r;
}
__device__ __forceinline__ float lo32(unsigned long long v) {
    return __uint_as_float((unsigned)(v & 0xffffffffull));
}
__device__ __forceinline__ float hi32(unsigned long long v) {
    return __uint_as_float((unsigned)(v >> 32));
}
__device__ __forceinline__ float tf32r(float x) {
    unsigned r;
    asm("cvt.rna.tf32.f32 %0, %1;" : "=r"(r) : "f"(x));
    return __uint_as_float(r);
}

// ---------------- tf32 rounding pass (for x) ----------------
__global__ void round_tf32_kernel(const float* __restrict__ in, float* __restrict__ out, int n4)
{
    int i = blockIdx.x * blockDim.x + threadIdx.x;
    if (i >= n4) return;
    float4 v = ((const float4*)in)[i];
    v.x = tf32r(v.x); v.y = tf32r(v.y); v.z = tf32r(v.z); v.w = tf32r(v.w);
    ((float4*)out)[i] = v;
}

// ---------------- W transpose + tf32 round:  in[k][n] (K=2048 rows) -> out[n][k], n padded ----------------
__global__ void transpose_tf32_kernel(const float* __restrict__ in, float* __restrict__ out,
                                      int N, int Npad)
{
    __shared__ float t[32][33];
    const int nb = blockIdx.x * 32;
    const int kb = blockIdx.y * 32;
    const int tx = threadIdx.x;
    const int ty = threadIdx.y;     // 0..7
    #pragma unroll
    for (int r = 0; r < 32; r += 8) {
        int n = nb + tx;
        t[ty + r][tx] = (n < N) ? tf32r(in[(size_t)(kb + ty + r) * N + n]) : 0.f;
    }
    __syncthreads();
    #pragma unroll
    for (int r = 0; r < 32; r += 8) {
        out[(size_t)(nb + ty + r) * DMODEL + kb + tx] = t[tx][ty + r];
    }
}

// ---------------- TF32 tensor-core GEMM ----------------
// C(M,N) = A(M,K) @ Bt(N,K)^T [+bias].  A row-major k-contig; Bt = B^T, row-major k-contig
// (Bt padded to Npad rows with zeros -> loaders unguarded).
// CTA: 512 thr, tile 128(M) x 256(N), BK=16, warp tile 32x64, 4-stage cp.async ring.
// All fragment loads via ldmatrix.x4.
#define STAGES      4
#define A_FLTS      (128 * 20)
#define B_FLTS      (256 * 20)
#define STAGE_FLTS  (A_FLTS + B_FLTS)                 // 7680 floats
#define GEMM_SMEM   (STAGES * STAGE_FLTS * 4)         // 122880 B

#define CP16(dst, src) \
    asm volatile("cp.async.cg.shared.global [%0], [%1], 16;\n" \
                 :: "r"(dst), "l"(src))

#define LDSM4(r0, r1, r2, r3, addr) \
    asm volatile("ldmatrix.sync.aligned.m8n8.x4.shared.b16 {%0,%1,%2,%3}, [%4];\n" \
                 : "=r"(r0), "=r"(r1), "=r"(r2), "=r"(r3) : "r"(addr))

__global__ void __launch_bounds__(512, 1)
mma_gemm(const float* __restrict__ A, const float* __restrict__ Bt,
         const float* __restrict__ bias, float* __restrict__ C,
         int M, int N, int K)
{
    extern __shared__ __align__(16) float smem[];

    const int tid  = threadIdx.x;
    const int bx   = blockIdx.x;   // N tile (256)
    const int by   = blockIdx.y;   // M tile (128)
    const int warp = tid >> 5;
    const int lane = tid & 31;
    const int g    = lane >> 2;
    const int t    = lane & 3;
    const int wm   = (warp & 3) * 32;
    const int wn   = (warp >> 2) * 64;

    // ---- cp.async loader mapping (no guards: Bt padded, M/K exact) ----
    const int arow  = tid >> 2;          // 0..127
    const int acseg = tid & 3;
    const float* Abase  = A  + (size_t)(by * 128 + arow) * K + acseg * 4;
    const float* Bbase  = Bt + (size_t)(bx * 256 + arow) * K + acseg * 4;   // rows 0..127
    const float* Bbase2 = Bbase + (size_t)128 * K;                          // rows 128..255

    unsigned sB = (unsigned)__cvta_generic_to_shared(&smem[0]);
    const unsigned aSt = sB + (unsigned)(arow * 20 + acseg * 4) * 4u;
    const unsigned bSt = sB + (unsigned)(A_FLTS + arow * 20 + acseg * 4) * 4u;
    const unsigned bSt2 = bSt + 128u * 20u * 4u;

#define ISSUE_TILE(kt) do {                                                    \
    const unsigned stOff = (unsigned)((kt) & (STAGES - 1)) * (STAGE_FLTS * 4u);\
    CP16(aSt  + stOff, Abase  + (size_t)(kt) * 16);                            \
    CP16(bSt  + stOff, Bbase  + (size_t)(kt) * 16);                            \
    CP16(bSt2 + stOff, Bbase2 + (size_t)(kt) * 16);                            \
    asm volatile("cp.async.commit_group;\n" ::: "memory");                     \
} while (0)

    // ---- ldmatrix per-lane address offsets (in floats) ----
    // A x4: m0 rows 0-7 k0..3 | m1 rows 8-15 k0..3 | m2 rows 0-7 k0+4.. | m3 rows 8-15 k0+4..
    const int aRowL = wm + (lane & 15);
    const int aColL = (lane >> 4) << 2;
    // B x4 (two j's): m0 n0..7,k0 | m1 n0..7,k0+4 | m2 n0+8..15,k0 | m3 n0+8..15,k0+4
    const int bRowL = (lane & 7) | ((lane & 16) >> 1);
    const int bColL = (lane & 8) ? 4 : 0;

    float c[16][4];
    #pragma unroll
    for (int i = 0; i < 16; i++)
        #pragma unroll
        for (int j = 0; j < 4; j++) c[i][j] = 0.f;

    const int nt = K >> 4;

    ISSUE_TILE(0);
    ISSUE_TILE(1);
    ISSUE_TILE(2);

    for (int kt = 0; kt < nt; kt++) {
        asm volatile("cp.async.wait_group 2;\n" ::: "memory");
        __syncthreads();

        if (kt + 3 < nt) {
            ISSUE_TILE(kt + 3);
        } else {
            asm volatile("cp.async.commit_group;\n" ::: "memory");
        }

        const unsigned stOff = (unsigned)(kt & (STAGES - 1)) * (STAGE_FLTS * 4u);
        const unsigned aBase = sB + stOff;
        const unsigned bBase = sB + stOff + A_FLTS * 4u;

        #pragma unroll
        for (int ks = 0; ks < 2; ks++) {
            const int k0 = ks * 8;
            unsigned a[2][4], b[8][2];
            #pragma unroll
            for (int i = 0; i < 2; i++) {
                unsigned addr = aBase + (unsigned)((aRowL + i * 16) * 20 + k0 + aColL) * 4u;
                LDSM4(a[i][0], a[i][1], a[i][2], a[i][3], addr);
            }
            #pragma unroll
            for (int jp = 0; jp < 4; jp++) {
                unsigned addr = bBase + (unsigned)((wn + jp * 16 + bRowL) * 20 + k0 + bColL) * 4u;
                LDSM4(b[2*jp][0], b[2*jp][1], b[2*jp+1][0], b[2*jp+1][1], addr);
            }
            #pragma unroll
            for (int i = 0; i < 2; i++)
                #pragma unroll
                for (int j = 0; j < 8; j++) {
                    asm volatile(
                        "mma.sync.aligned.m16n8k8.row.col.f32.tf32.tf32.f32 "
                        "{%0,%1,%2,%3}, {%4,%5,%6,%7}, {%8,%9}, {%0,%1,%2,%3};\n"
                        : "+f"(c[i*8+j][0]), "+f"(c[i*8+j][1]),
                          "+f"(c[i*8+j][2]), "+f"(c[i*8+j][3])
                        : "r"(a[i][0]), "r"(a[i][1]), "r"(a[i][2]), "r"(a[i][3]),
                          "r"(b[j][0]), "r"(b[j][1]));
                }
        }
    }

    // ---- epilogue ----
    #pragma unroll
    for (int i = 0; i < 2; i++) {
        #pragma unroll
        for (int j = 0; j < 8; j++) {
            const int row = by * 128 + wm + i * 16 + g;
            const int col = bx * 256 + wn + j * 8 + 2 * t;
            if (col < N) {
                float b0 = 0.f, b1 = 0.f;
                if (bias) { b0 = __ldg(&bias[col]); b1 = __ldg(&bias[col + 1]); }
                float2 v0 = make_float2(c[i*8+j][0] + b0, c[i*8+j][1] + b1);
                float2 v1 = make_float2(c[i*8+j][2] + b0, c[i*8+j][3] + b1);
                *(float2*)&C[(size_t)row * N + col]       = v0;
                *(float2*)&C[(size_t)(row + 8) * N + col] = v1;
            }
        }
    }
#undef ISSUE_TILE
}

// ---------------- causal depthwise conv1d (K=4) + SiLU ----------------
__global__ void conv_silu_kernel(const float* __restrict__ conv_w,
                                 const float* __restrict__ conv_b)
{
    int idx = blockIdx.x * blockDim.x + threadIdx.x;
    if (idx >= BL * CONVDIM) return;
    int c = idx % CONVDIM;
    int m = idx / CONVDIM;       // b*L + l
    int l = m % LSEQ;

    float acc = conv_b[c];
    #pragma unroll
    for (int k = 0; k < KCONV; k++) {
        int lk = l - (KCONV - 1) + k;
        if (lk >= 0) {
            acc += g_proj[(size_t)(m - (KCONV - 1) + k) * PROJW + DMODEL + c]
                   * conv_w[c * KCONV + k];
        }
    }
    acc = acc / (1.f + expf(-acc));
    g_conv[(size_t)m * CONVDIM + c] = acc;
}

// ---------------- dt = softplus(dt_raw + bias), dA = exp(dt*A) ----------------
__global__ void dt_kernel(const float* __restrict__ A_log,
                          const float* __restrict__ dt_bias)
{
    int idx = blockIdx.x * blockDim.x + threadIdx.x;
    if (idx >= BL * HEADS) return;
    int h = idx % HEADS;
    int m = idx / HEADS;
    int b = m / LSEQ;
    int l = m % LSEQ;

    float raw = g_proj[(size_t)m * PROJW + DMODEL + CONVDIM + h] + dt_bias[h];
    float dt  = (raw > 20.f) ? raw : log1pf(expf(raw));
    float dA  = expf(dt * (-expf(A_log[h])));
    size_t o  = ((size_t)(b * HEADS + h)) * LSEQ + l;
    g_dt[o] = dt;
    g_dA[o] = dA;
}

// ---------------- selective scan ----------------
#define SD 8

__global__ __launch_bounds__(128, 1)
void scan_kernel(const float* __restrict__ D_param)
{
    const int h   = blockIdx.x;
    const int b   = blockIdx.y;
    const int tid = threadIdx.x;

    __shared__ float s_dt[LSEQ];
    __shared__ float s_dA[LSEQ];
    __shared__ __align__(16) float s_pipe[SD][128];

    {
        const float* dtp = g_dt + ((size_t)(b * HEADS + h)) * LSEQ;
        const float* dAp = g_dA + ((size_t)(b * HEADS + h)) * LSEQ;
        for (int i = tid; i < LSEQ; i += 128) {
            s_dt[i] = dtp[i];
            s_dA[i] = dAp[i];
        }
    }

    const int p    = tid >> 1;
    const int half = tid & 1;
    const float Dh = D_param[h];

    unsigned long long hs[8];
    #pragma unroll
    for (int i = 0; i < 8; i++) hs[i] = 0ull;

    const bool loader = (tid < 32);
    size_t srcoff = 0; int dstoff = 0;
    if (loader) {
        if (tid < 16) { srcoff = (size_t)h * HDIM + tid * 4; dstoff = tid * 4; }
        else          { srcoff = (size_t)DMODEL + (tid - 16) * 4; dstoff = 64 + (tid - 16) * 4; }
    }
    const float* convb = g_conv + (size_t)b * LSEQ * CONVDIM;
    unsigned sbase = (unsigned)__cvta_generic_to_shared(&s_pipe[0][0]);

    #pragma unroll
    for (int tt = 0; tt < SD - 1; tt++) {
        if (loader) {
            const float* src = convb + (size_t)tt * CONVDIM + srcoff;
            unsigned dst = sbase + (unsigned)((tt & (SD - 1)) * 128 + dstoff) * 4u;
            asm volatile("cp.async.ca.shared.global [%0], [%1], 16;\n"
                         :: "r"(dst), "l"(src));
        }
        asm volatile("cp.async.commit_group;\n" ::: "memory");
    }

    float* yout = g_y + (size_t)b * LSEQ * DMODEL + h * HDIM + p;

    for (int tc = 0; tc < LSEQ; tc++) {
        asm volatile("cp.async.wait_group 6;\n" ::: "memory");
        __syncthreads();

        const int nt = tc + SD - 1;
        if (loader && nt < LSEQ) {
            const float* src = convb + (size_t)nt * CONVDIM + srcoff;
            unsigned dst = sbase + (unsigned)((nt & (SD - 1)) * 128 + dstoff) * 4u;
            asm volatile("cp.async.ca.shared.global [%0], [%1], 16;\n"
                         :: "r"(dst), "l"(src));
        }
        asm volatile("cp.async.commit_group;\n" ::: "memory");

        const float* sl = s_pipe[tc & (SD - 1)];
        float xv  = sl[p];
        float dtv = s_dt[tc];
        float dav = s_dA[tc];
        float coef = dtv * xv;
        unsigned long long c2 = pack2(coef, coef);
        unsigned long long d2 = pack2(dav, dav);
        const unsigned long long* B2 = (const unsigned long long*)(sl + 64) + half * 8;
        const unsigned long long* C2 = (const unsigned long long*)(sl + 96) + half * 8;

        unsigned long long acc0 = 0ull, acc1 = 0ull;
        #pragma unroll
        for (int i = 0; i < 8; i++) {
            unsigned long long u = mul2(c2, B2[i]);
            hs[i] = fma2v(d2, hs[i], u);
            if (i & 1) acc1 = fma2v(hs[i], C2[i], acc1);
            else       acc0 = fma2v(hs[i], C2[i], acc0);
        }
        unsigned long long s = add2(acc0, acc1);
        float mine = lo32(s) + hi32(s);
        float other = __shfl_xor_sync(0xffffffffu, mine, 1);
        if (half == 0) {
            yout[(size_t)tc * DMODEL] = mine + other + Dh * xv;
        }
    }
}

// ---------------- gated RMSNorm (in place; output tf32-rounded for GEMM2) ----------------
__global__ void __launch_bounds__(256)
rmsnorm_kernel(const float* __restrict__ norm_w)
{
    const int m   = blockIdx.x;
    const int tid = threadIdx.x;
    float*       yrow = g_y    + (size_t)m * DMODEL;
    const float* grow = g_proj + (size_t)m * PROJW;   // gate = proj[:, 0:2048]

    float v[8];
    float ss = 0.f;
    #pragma unroll
    for (int k = 0; k < 8; k++) {
        int j = tid + k * 256;
        float gt  = grow[j];
        float val = yrow[j] * (gt / (1.f + expf(-gt)));
        v[k] = val;
        ss += val * val;
    }
    #pragma unroll
    for (int o = 16; o > 0; o >>= 1) ss += __shfl_xor_sync(0xffffffffu, ss, o);

    __shared__ float sred[8];
    if ((tid & 31) == 0) sred[tid >> 5] = ss;
    __syncthreads();
    float tot = sred[0] + sred[1] + sred[2] + sred[3]
              + sred[4] + sred[5] + sred[6] + sred[7];
    float scale = rsqrtf(tot * (1.f / DMODEL) + 1e-6f);

    #pragma unroll
    for (int k = 0; k < 8; k++) {
        int j = tid + k * 256;
        yrow[j] = tf32r(v[k] * scale * norm_w[j]);
    }
}

// ---------------- launch ----------------
extern "C" void kernel_launch(void* const* d_in, const int* in_sizes, int n_in,
                              void* d_out, int out_size)
{
    const float* x       = (const float*)d_in[0];
    const float* W_in    = (const float*)d_in[1];
    const float* b_in    = (const float*)d_in[2];
    const float* conv_w  = (const float*)d_in[3];
    const float* conv_b  = (const float*)d_in[4];
    const float* A_log   = (const float*)d_in[5];
    const float* dt_bias = (const float*)d_in[6];
    const float* D_par   = (const float*)d_in[7];
    const float* norm_w  = (const float*)d_in[8];
    const float* W_out   = (const float*)d_in[9];
    float* out = (float*)d_out;

    float *proj, *yb, *xa, *wa, *wb;
    cudaGetSymbolAddress((void**)&proj, g_proj);
    cudaGetSymbolAddress((void**)&yb,   g_y);
    cudaGetSymbolAddress((void**)&xa,   g_xa);
    cudaGetSymbolAddress((void**)&wa,   g_wa);
    cudaGetSymbolAddress((void**)&wb,   g_wb);

    cudaFuncSetAttribute(mma_gemm, cudaFuncAttributeMaxDynamicSharedMemorySize,
                         GEMM_SMEM);

    // 0) tf32-round x; transpose+round W_in -> wa (padded), W_out -> wb
    {
        int n4x = (BL * DMODEL) / 4;
        round_tf32_kernel<<<(n4x + 255) / 256, 256>>>(x, xa, n4x);
        dim3 blk(32, 8);
        transpose_tf32_kernel<<<dim3(PROJPAD / 32, DMODEL / 32), blk>>>(W_in, wa, PROJW, PROJPAD);
        transpose_tf32_kernel<<<dim3(DMODEL / 32, DMODEL / 32), blk>>>(W_out, wb, DMODEL, DMODEL);
    }
    // 1) proj = x @ W_in + b_in        (8192 x 4192, K=2048)
    {
        dim3 grid(PROJPAD / 256, BL / 128);
        mma_gemm<<<grid, 512, GEMM_SMEM>>>(xa, wa, b_in, proj, BL, PROJW, DMODEL);
    }
    // 2) causal depthwise conv + SiLU
    {
        int total = BL * CONVDIM;
        conv_silu_kernel<<<(total + 255) / 256, 256>>>(conv_w, conv_b);
    }
    // 3) dt / dA
    {
        int total = BL * HEADS;
        dt_kernel<<<(total + 255) / 256, 256>>>(A_log, dt_bias);
    }
    // 4) selective scan (+ D skip)
    scan_kernel<<<dim3(HEADS, BATCH), 128>>>(D_par);
    // 5) gated RMSNorm (tf32-rounds y)
    rmsnorm_kernel<<<BL, 256>>>(norm_w);
    // 6) out = y @ W_out               (8192 x 2048, K=2048)
    {
        dim3 grid(DMODEL / 256, BL / 128);
        mma_gemm<<<grid, 512, GEMM_SMEM>>>(yb, wb, nullptr, out, BL, DMODEL, DMODEL);
    }
}

// round 6
// speedup vs baseline: 1.1706x; 1.1706x over previous
#include <cuda_runtime.h>
#include <cstdint>
#include <cstddef>

// ---------------- problem constants ----------------
#define HEADS   32
#define HDIM    64      // P
#define NSTATE  32
#define KCONV   4
#define DMODEL  2048
#define CONVDIM 2112
#define PROJW   4192
#define BATCH   4
#define LSEQ    2048
#define BL      (BATCH * LSEQ)   // 8192
#define PROJPAD 4352             // padded N for GEMM1 B operand (multiple of 128)

// ---------------- scratch (device globals; no runtime alloc) ----------------
__device__ float g_proj[(size_t)BL * PROJW];       // 137 MB
__device__ float g_conv[(size_t)BL * CONVDIM];     // 69 MB
__device__ float g_dt  [(size_t)BATCH * HEADS * LSEQ];
__device__ float g_dA  [(size_t)BATCH * HEADS * LSEQ];
__device__ float g_y   [(size_t)BL * DMODEL];      // 67 MB (tf32-rounded by rmsnorm)
__device__ float g_xa  [(size_t)BL * DMODEL];      // tf32-rounded x
__device__ float g_wa  [(size_t)PROJPAD * DMODEL]; // tf32-rounded W_in^T, padded rows
__device__ float g_wb  [(size_t)DMODEL * DMODEL];  // tf32-rounded W_out^T

// ---------------- packed fp32x2 helpers ----------------
__device__ __forceinline__ unsigned long long pack2(float lo, float hi) {
    unsigned long long r;
    asm("mov.b64 %0, {%1, %2};" : "=l"(r) : "f"(lo), "f"(hi));
    return r;
}
__device__ __forceinline__ unsigned long long mul2(unsigned long long a, unsigned long long b) {
    unsigned long long r;
    asm("mul.rn.f32x2 %0, %1, %2;" : "=l"(r) : "l"(a), "l"(b));
    return r;
}
__device__ __forceinline__ unsigned long long fma2v(unsigned long long a, unsigned long long b,
                                                    unsigned long long c) {
    unsigned long long r;
    asm("fma.rn.f32x2 %0, %1, %2, %3;" : "=l"(r) : "l"(a), "l"(b), "l"(c));
    return r;
}
__device__ __forceinline__ unsigned long long add2(unsigned long long a, unsigned long long b) {
    unsigned long long r;
    asm("add.rn.f32x2 %0, %1, %2;" : "=l"(r) : "l"(a), "l"(b));
    return r;
}
__device__ __forceinline__ float lo32(unsigned long long v) {
    return __uint_as_float((unsigned)(v & 0xffffffffull));
}
__device__ __forceinline__ float hi32(unsigned long long v) {
    return __uint_as_float((unsigned)(v >> 32));
}
__device__ __forceinline__ float tf32r(float x) {
    unsigned r;
    asm("cvt.rna.tf32.f32 %0, %1;" : "=r"(r) : "f"(x));
    return __uint_as_float(r);
}

// ---------------- tf32 rounding pass (for x) ----------------
__global__ void round_tf32_kernel(const float* __restrict__ in, float* __restrict__ out, int n4)
{
    int i = blockIdx.x * blockDim.x + threadIdx.x;
    if (i >= n4) return;
    float4 v = ((const float4*)in)[i];
    v.x = tf32r(v.x); v.y = tf32r(v.y); v.z = tf32r(v.z); v.w = tf32r(v.w);
    ((float4*)out)[i] = v;
}

// ---------------- W transpose + tf32 round:  in[k][n] -> out[n][k], n padded with zeros ----------------
__global__ void transpose_tf32_kernel(const float* __restrict__ in, float* __restrict__ out,
                                      int N, int Npad)
{
    __shared__ float t[32][33];
    const int nb = blockIdx.x * 32;
    const int kb = blockIdx.y * 32;
    const int tx = threadIdx.x;
    const int ty = threadIdx.y;     // 0..7
    #pragma unroll
    for (int r = 0; r < 32; r += 8) {
        int n = nb + tx;
        t[ty + r][tx] = (n < N) ? tf32r(in[(size_t)(kb + ty + r) * N + n]) : 0.f;
    }
    __syncthreads();
    #pragma unroll
    for (int r = 0; r < 32; r += 8) {
        out[(size_t)(nb + ty + r) * DMODEL + kb + tx] = t[tx][ty + r];
    }
}

// ---------------- TF32 tensor-core GEMM ----------------
// C(M,N) = A(M,K) @ Bt(N,K)^T [+bias].  A row-major k-contig; Bt = B^T row-major
// k-contig, padded to multiple of 128 rows -> unguarded loaders.
// CTA: 256 thr, tile 128x128, BK=16, warp tile 64x32 (8 warps), 4-stage cp.async
// ring, one __syncthreads per k-tile, 2 CTAs/SM. All frag loads via ldmatrix.x4.
#define STAGES      4
#define A_FLTS      (128 * 20)
#define STAGE_FLTS  (2 * A_FLTS)                       // 5120 floats
#define GEMM_SMEM   (STAGES * STAGE_FLTS * 4)          // 81920 B

#define CP16(dst, src) \
    asm volatile("cp.async.cg.shared.global [%0], [%1], 16;\n" \
                 :: "r"(dst), "l"(src))

#define LDSM4(r0, r1, r2, r3, addr) \
    asm volatile("ldmatrix.sync.aligned.m8n8.x4.shared.b16 {%0,%1,%2,%3}, [%4];\n" \
                 : "=r"(r0), "=r"(r1), "=r"(r2), "=r"(r3) : "r"(addr))

__global__ void __launch_bounds__(256, 2)
mma_gemm(const float* __restrict__ A, const float* __restrict__ Bt,
         const float* __restrict__ bias, float* __restrict__ C,
         int M, int N, int K)
{
    extern __shared__ __align__(16) float smem[];

    const int tid  = threadIdx.x;
    const int bx   = blockIdx.x;   // N tile (128)
    const int by   = blockIdx.y;   // M tile (128)
    const int warp = tid >> 5;
    const int lane = tid & 31;
    const int g    = lane >> 2;
    const int t    = lane & 3;
    const int wm   = (warp & 1) * 64;
    const int wn   = (warp >> 1) * 32;

    // ---- cp.async loader mapping (no guards: Bt padded, M/K exact) ----
    const int arow  = tid >> 2;          // 0..63  (second pass: +64)
    const int acseg = tid & 3;
    const float* Abase  = A  + (size_t)(by * 128 + arow) * K + acseg * 4;
    const float* Abase2 = Abase + (size_t)64 * K;
    const float* Bbase  = Bt + (size_t)(bx * 128 + arow) * K + acseg * 4;
    const float* Bbase2 = Bbase + (size_t)64 * K;

    unsigned sB = (unsigned)__cvta_generic_to_shared(&smem[0]);
    const unsigned aSt  = sB + (unsigned)(arow * 20 + acseg * 4) * 4u;
    const unsigned aSt2 = aSt + 64u * 20u * 4u;
    const unsigned bSt  = sB + (unsigned)(A_FLTS + arow * 20 + acseg * 4) * 4u;
    const unsigned bSt2 = bSt + 64u * 20u * 4u;

#define ISSUE_TILE(kt) do {                                                    \
    const unsigned stOff = (unsigned)((kt) & (STAGES - 1)) * (STAGE_FLTS * 4u);\
    CP16(aSt  + stOff, Abase  + (size_t)(kt) * 16);                            \
    CP16(aSt2 + stOff, Abase2 + (size_t)(kt) * 16);                            \
    CP16(bSt  + stOff, Bbase  + (size_t)(kt) * 16);                            \
    CP16(bSt2 + stOff, Bbase2 + (size_t)(kt) * 16);                            \
    asm volatile("cp.async.commit_group;\n" ::: "memory");                     \
} while (0)

    // ---- ldmatrix per-lane source rows/cols (in floats) ----
    const int aRowL = (lane & 15);               // + wm + i*16
    const int aColL = (lane >> 4) << 2;          // 0 or 4
    const int bRowL = (lane & 7) | ((lane & 16) >> 1);   // + wn + jp*16
    const int bColL = (lane & 8) ? 4 : 0;

    float c[16][4];
    #pragma unroll
    for (int i = 0; i < 16; i++)
        #pragma unroll
        for (int j = 0; j < 4; j++) c[i][j] = 0.f;

    const int nt = K >> 4;

    ISSUE_TILE(0);
    ISSUE_TILE(1);
    ISSUE_TILE(2);

    for (int kt = 0; kt < nt; kt++) {
        asm volatile("cp.async.wait_group 2;\n" ::: "memory");
        __syncthreads();

        if (kt + 3 < nt) {
            ISSUE_TILE(kt + 3);
        } else {
            asm volatile("cp.async.commit_group;\n" ::: "memory");
        }

        const unsigned stOff = (unsigned)(kt & (STAGES - 1)) * (STAGE_FLTS * 4u);
        const unsigned aBase = sB + stOff;
        const unsigned bBase = aBase + A_FLTS * 4u;

        #pragma unroll
        for (int ks = 0; ks < 2; ks++) {
            const int k0 = ks * 8;
            unsigned a[4][4], b[4][2];
            #pragma unroll
            for (int i = 0; i < 4; i++) {
                unsigned addr = aBase +
                    (unsigned)((wm + i * 16 + aRowL) * 20 + k0 + aColL) * 4u;
                LDSM4(a[i][0], a[i][1], a[i][2], a[i][3], addr);
            }
            #pragma unroll
            for (int jp = 0; jp < 2; jp++) {
                unsigned addr = bBase +
                    (unsigned)((wn + jp * 16 + bRowL) * 20 + k0 + bColL) * 4u;
                LDSM4(b[2*jp][0], b[2*jp][1], b[2*jp+1][0], b[2*jp+1][1], addr);
            }
            #pragma unroll
            for (int i = 0; i < 4; i++)
                #pragma unroll
                for (int j = 0; j < 4; j++) {
                    asm volatile(
                        "mma.sync.aligned.m16n8k8.row.col.f32.tf32.tf32.f32 "
                        "{%0,%1,%2,%3}, {%4,%5,%6,%7}, {%8,%9}, {%0,%1,%2,%3};\n"
                        : "+f"(c[i*4+j][0]), "+f"(c[i*4+j][1]),
                          "+f"(c[i*4+j][2]), "+f"(c[i*4+j][3])
                        : "r"(a[i][0]), "r"(a[i][1]), "r"(a[i][2]), "r"(a[i][3]),
                          "r"(b[j][0]), "r"(b[j][1]));
                }
        }
    }

    // ---- epilogue ----
    #pragma unroll
    for (int i = 0; i < 4; i++) {
        #pragma unroll
        for (int j = 0; j < 4; j++) {
            const int row = by * 128 + wm + i * 16 + g;
            const int col = bx * 128 + wn + j * 8 + 2 * t;
            if (col < N) {
                float b0 = 0.f, b1 = 0.f;
                if (bias) { b0 = __ldg(&bias[col]); b1 = __ldg(&bias[col + 1]); }
                float2 v0 = make_float2(c[i*4+j][0] + b0, c[i*4+j][1] + b1);
                float2 v1 = make_float2(c[i*4+j][2] + b0, c[i*4+j][3] + b1);
                *(float2*)&C[(size_t)row * N + col]       = v0;
                *(float2*)&C[(size_t)(row + 8) * N + col] = v1;
            }
        }
    }
#undef ISSUE_TILE
}

// ---------------- causal depthwise conv1d (K=4) + SiLU ----------------
__global__ void conv_silu_kernel(const float* __restrict__ conv_w,
                                 const float* __restrict__ conv_b)
{
    int idx = blockIdx.x * blockDim.x + threadIdx.x;
    if (idx >= BL * CONVDIM) return;
    int c = idx % CONVDIM;
    int m = idx / CONVDIM;       // b*L + l
    int l = m % LSEQ;

    float acc = conv_b[c];
    #pragma unroll
    for (int k = 0; k < KCONV; k++) {
        int lk = l - (KCONV - 1) + k;
        if (lk >= 0) {
            acc += g_proj[(size_t)(m - (KCONV - 1) + k) * PROJW + DMODEL + c]
                   * conv_w[c * KCONV + k];
        }
    }
    acc = acc / (1.f + expf(-acc));
    g_conv[(size_t)m * CONVDIM + c] = acc;
}

// ---------------- dt = softplus(dt_raw + bias), dA = exp(dt*A) ----------------
__global__ void dt_kernel(const float* __restrict__ A_log,
                          const float* __restrict__ dt_bias)
{
    int idx = blockIdx.x * blockDim.x + threadIdx.x;
    if (idx >= BL * HEADS) return;
    int h = idx % HEADS;
    int m = idx / HEADS;
    int b = m / LSEQ;
    int l = m % LSEQ;

    float raw = g_proj[(size_t)m * PROJW + DMODEL + CONVDIM + h] + dt_bias[h];
    float dt  = (raw > 20.f) ? raw : log1pf(expf(raw));
    float dA  = expf(dt * (-expf(A_log[h])));
    size_t o  = ((size_t)(b * HEADS + h)) * LSEQ + l;
    g_dt[o] = dt;
    g_dA[o] = dA;
}

// ---------------- selective scan ----------------
#define SD 8

__global__ __launch_bounds__(128, 1)
void scan_kernel(const float* __restrict__ D_param)
{
    const int h   = blockIdx.x;
    const int b   = blockIdx.y;
    const int tid = threadIdx.x;

    __shared__ float s_dt[LSEQ];
    __shared__ float s_dA[LSEQ];
    __shared__ __align__(16) float s_pipe[SD][128];

    {
        const float* dtp = g_dt + ((size_t)(b * HEADS + h)) * LSEQ;
        const float* dAp = g_dA + ((size_t)(b * HEADS + h)) * LSEQ;
        for (int i = tid; i < LSEQ; i += 128) {
            s_dt[i] = dtp[i];
            s_dA[i] = dAp[i];
        }
    }

    const int p    = tid >> 1;
    const int half = tid & 1;
    const float Dh = D_param[h];

    unsigned long long hs[8];
    #pragma unroll
    for (int i = 0; i < 8; i++) hs[i] = 0ull;

    const bool loader = (tid < 32);
    size_t srcoff = 0; int dstoff = 0;
    if (loader) {
        if (tid < 16) { srcoff = (size_t)h * HDIM + tid * 4; dstoff = tid * 4; }
        else          { srcoff = (size_t)DMODEL + (tid - 16) * 4; dstoff = 64 + (tid - 16) * 4; }
    }
    const float* convb = g_conv + (size_t)b * LSEQ * CONVDIM;
    unsigned sbase = (unsigned)__cvta_generic_to_shared(&s_pipe[0][0]);

    #pragma unroll
    for (int tt = 0; tt < SD - 1; tt++) {
        if (loader) {
            const float* src = convb + (size_t)tt * CONVDIM + srcoff;
            unsigned dst = sbase + (unsigned)((tt & (SD - 1)) * 128 + dstoff) * 4u;
            asm volatile("cp.async.ca.shared.global [%0], [%1], 16;\n"
                         :: "r"(dst), "l"(src));
        }
        asm volatile("cp.async.commit_group;\n" ::: "memory");
    }

    float* yout = g_y + (size_t)b * LSEQ * DMODEL + h * HDIM + p;

    for (int tc = 0; tc < LSEQ; tc++) {
        asm volatile("cp.async.wait_group 6;\n" ::: "memory");
        __syncthreads();

        const int nt = tc + SD - 1;
        if (loader && nt < LSEQ) {
            const float* src = convb + (size_t)nt * CONVDIM + srcoff;
            unsigned dst = sbase + (unsigned)((nt & (SD - 1)) * 128 + dstoff) * 4u;
            asm volatile("cp.async.ca.shared.global [%0], [%1], 16;\n"
                         :: "r"(dst), "l"(src));
        }
        asm volatile("cp.async.commit_group;\n" ::: "memory");

        const float* sl = s_pipe[tc & (SD - 1)];
        float xv  = sl[p];
        float dtv = s_dt[tc];
        float dav = s_dA[tc];
        float coef = dtv * xv;
        unsigned long long c2 = pack2(coef, coef);
        unsigned long long d2 = pack2(dav, dav);
        const unsigned long long* B2 = (const unsigned long long*)(sl + 64) + half * 8;
        const unsigned long long* C2 = (const unsigned long long*)(sl + 96) + half * 8;

        unsigned long long acc0 = 0ull, acc1 = 0ull;
        #pragma unroll
        for (int i = 0; i < 8; i++) {
            unsigned long long u = mul2(c2, B2[i]);
            hs[i] = fma2v(d2, hs[i], u);
            if (i & 1) acc1 = fma2v(hs[i], C2[i], acc1);
            else       acc0 = fma2v(hs[i], C2[i], acc0);
        }
        unsigned long long s = add2(acc0, acc1);
        float mine = lo32(s) + hi32(s);
        float other = __shfl_xor_sync(0xffffffffu, mine, 1);
        if (half == 0) {
            yout[(size_t)tc * DMODEL] = mine + other + Dh * xv;
        }
    }
}

// ---------------- gated RMSNorm (in place; output tf32-rounded for GEMM2) ----------------
__global__ void __launch_bounds__(256)
rmsnorm_kernel(const float* __restrict__ norm_w)
{
    const int m   = blockIdx.x;
    const int tid = threadIdx.x;
    float*       yrow = g_y    + (size_t)m * DMODEL;
    const float* grow = g_proj + (size_t)m * PROJW;   // gate = proj[:, 0:2048]

    float v[8];
    float ss = 0.f;
    #pragma unroll
    for (int k = 0; k < 8; k++) {
        int j = tid + k * 256;
        float gt  = grow[j];
        float val = yrow[j] * (gt / (1.f + expf(-gt)));
        v[k] = val;
        ss += val * val;
    }
    #pragma unroll
    for (int o = 16; o > 0; o >>= 1) ss += __shfl_xor_sync(0xffffffffu, ss, o);

    __shared__ float sred[8];
    if ((tid & 31) == 0) sred[tid >> 5] = ss;
    __syncthreads();
    float tot = sred[0] + sred[1] + sred[2] + sred[3]
              + sred[4] + sred[5] + sred[6] + sred[7];
    float scale = rsqrtf(tot * (1.f / DMODEL) + 1e-6f);

    #pragma unroll
    for (int k = 0; k < 8; k++) {
        int j = tid + k * 256;
        yrow[j] = tf32r(v[k] * scale * norm_w[j]);
    }
}

// ---------------- launch ----------------
extern "C" void kernel_launch(void* const* d_in, const int* in_sizes, int n_in,
                              void* d_out, int out_size)
{
    const float* x       = (const float*)d_in[0];
    const float* W_in    = (const float*)d_in[1];
    const float* b_in    = (const float*)d_in[2];
    const float* conv_w  = (const float*)d_in[3];
    const float* conv_b  = (const float*)d_in[4];
    const float* A_log   = (const float*)d_in[5];
    const float* dt_bias = (const float*)d_in[6];
    const float* D_par   = (const float*)d_in[7];
    const float* norm_w  = (const float*)d_in[8];
    const float* W_out   = (const float*)d_in[9];
    float* out = (float*)d_out;

    float *proj, *yb, *xa, *wa, *wb;
    cudaGetSymbolAddress((void**)&proj, g_proj);
    cudaGetSymbolAddress((void**)&yb,   g_y);
    cudaGetSymbolAddress((void**)&xa,   g_xa);
    cudaGetSymbolAddress((void**)&wa,   g_wa);
    cudaGetSymbolAddress((void**)&wb,   g_wb);

    cudaFuncSetAttribute(mma_gemm, cudaFuncAttributeMaxDynamicSharedMemorySize,
                         GEMM_SMEM);

    // 0) tf32-round x; transpose+round W_in -> wa (padded), W_out -> wb
    {
        int n4x = (BL * DMODEL) / 4;
        round_tf32_kernel<<<(n4x + 255) / 256, 256>>>(x, xa, n4x);
        dim3 blk(32, 8);
        transpose_tf32_kernel<<<dim3(PROJPAD / 32, DMODEL / 32), blk>>>(W_in, wa, PROJW, PROJPAD);
        transpose_tf32_kernel<<<dim3(DMODEL / 32, DMODEL / 32), blk>>>(W_out, wb, DMODEL, DMODEL);
    }
    // 1) proj = x @ W_in + b_in        (8192 x 4192, K=2048)
    {
        dim3 grid(PROJPAD / 128, BL / 128);
        mma_gemm<<<grid, 256, GEMM_SMEM>>>(xa, wa, b_in, proj, BL, PROJW, DMODEL);
    }
    // 2) causal depthwise conv + SiLU
    {
        int total = BL * CONVDIM;
        conv_silu_kernel<<<(total + 255) / 256, 256>>>(conv_w, conv_b);
    }
    // 3) dt / dA
    {
        int total = BL * HEADS;
        dt_kernel<<<(total + 255) / 256, 256>>>(A_log, dt_bias);
    }
    // 4) selective scan (+ D skip)
    scan_kernel<<<dim3(HEADS, BATCH), 128>>>(D_par);
    // 5) gated RMSNorm (tf32-rounds y)
    rmsnorm_kernel<<<BL, 256>>>(norm_w);
    // 6) out = y @ W_out               (8192 x 2048, K=2048)
    {
        dim3 grid(DMODEL / 128, BL / 128);
        mma_gemm<<<grid, 256, GEMM_SMEM>>>(yb, wb, nullptr, out, BL, DMODEL, DMODEL);
    }
}

// round 11
// speedup vs baseline: 1.3811x; 1.1798x over previous
#include <cuda_runtime.h>
#include <cstdint>
#include <cstddef>

// ---------------- problem constants ----------------
#define HEADS   32
#define HDIM    64
#define NSTATE  32
#define KCONV   4
#define DMODEL  2048
#define CONVDIM 2112
#define PROJW   4192
#define BATCH   4
#define LSEQ    2048
#define BL      (BATCH * LSEQ)   // 8192
#define PROJPAD 4352             // padded N for GEMM1 (34 * 128)
#define NKT     128              // K / 16 k-tiles

// ---------------- scratch (device globals; no runtime alloc) ----------------
__device__ float g_proj[(size_t)BL * PROJW];       // 137 MB
__device__ float g_conv[(size_t)BL * CONVDIM];     // 69 MB
__device__ float g_dt  [(size_t)BATCH * HEADS * LSEQ];
__device__ float g_dA  [(size_t)BATCH * HEADS * LSEQ];
__device__ float g_y   [(size_t)BL * DMODEL];      // scan output (fp32 rows)
__device__ float g_xa  [(size_t)BL * DMODEL];      // packed tf32 x   [mb][kt][tile]
__device__ float g_ya  [(size_t)BL * DMODEL];      // packed tf32 y   [mb][kt][tile]
__device__ float g_wa  [(size_t)PROJPAD * DMODEL]; // packed tf32 W_in^T
__device__ float g_wb  [(size_t)DMODEL * DMODEL];  // packed tf32 W_out^T

// ---------------- packed fp32x2 helpers (scan) ----------------
__device__ __forceinline__ unsigned long long pack2(float lo, float hi) {
    unsigned long long r;
    asm("mov.b64 %0, {%1, %2};" : "=l"(r) : "f"(lo), "f"(hi));
    return r;
}
__device__ __forceinline__ unsigned long long mul2(unsigned long long a, unsigned long long b) {
    unsigned long long r;
    asm("mul.rn.f32x2 %0, %1, %2;" : "=l"(r) : "l"(a), "l"(b));
    return r;
}
__device__ __forceinline__ unsigned long long fma2v(unsigned long long a, unsigned long long b,
                                                    unsigned long long c) {
    unsigned long long r;
    asm("fma.rn.f32x2 %0, %1, %2, %3;" : "=l"(r) : "l"(a), "l"(b), "l"(c));
    return r;
}
__device__ __forceinline__ unsigned long long add2(unsigned long long a, unsigned long long b) {
    unsigned long long r;
    asm("add.rn.f32x2 %0, %1, %2;" : "=l"(r) : "l"(a), "l"(b));
    return r;
}
__device__ __forceinline__ float lo32(unsigned long long v) {
    return __uint_as_float((unsigned)(v & 0xffffffffull));
}
__device__ __forceinline__ float hi32(unsigned long long v) {
    return __uint_as_float((unsigned)(v >> 32));
}
__device__ __forceinline__ float tf32r(float x) {
    unsigned r;
    asm("cvt.rna.tf32.f32 %0, %1;" : "=r"(r) : "f"(x));
    return __uint_as_float(r);
}

// packed-tile float offset for element (global row r128-block handled by caller)
// r = row within 128-block, kt = k-tile, s = 16B seg (k>>2)&3, e = k&3
__device__ __forceinline__ size_t pk_off(int blk, int kt, int r, int s, int e) {
    return (((size_t)blk * NKT + kt) << 11) + (size_t)r * 16 +
           (size_t)(((s + (r >> 1)) & 3) << 2) + e;
}

// ---------------- x -> packed tf32 ----------------
__global__ void round_pack_kernel(const float* __restrict__ in, float* __restrict__ out)
{
    int i = blockIdx.x * blockDim.x + threadIdx.x;   // one 16B seg
    if (i >= BL * DMODEL / 4) return;
    int m  = i >> 9;           // row (DMODEL/4 = 512 segs/row)
    int sj = i & 511;
    int kt = sj >> 2, s = sj & 3;
    int mb = m >> 7,  r = m & 127;
    float4 v = ((const float4*)in)[i];
    v.x = tf32r(v.x); v.y = tf32r(v.y); v.z = tf32r(v.z); v.w = tf32r(v.w);
    size_t d = pk_off(mb, kt, r, s, 0);
    *(float4*)(out + d) = v;
}

// ---------------- W[k][n] -> packed tf32 of W^T (n-major), rows padded 0 ----------------
__global__ void transpose_pack_kernel(const float* __restrict__ in, float* __restrict__ out,
                                      int N)
{
    __shared__ float t[32][33];
    const int nb = blockIdx.x * 32;
    const int kb = blockIdx.y * 32;
    const int tx = threadIdx.x;
    const int ty = threadIdx.y;     // 0..7
    #pragma unroll
    for (int rr = 0; rr < 32; rr += 8) {
        int n = nb + tx;
        t[ty + rr][tx] = (n < N) ? tf32r(in[(size_t)(kb + ty + rr) * N + n]) : 0.f;
    }
    __syncthreads();
    #pragma unroll
    for (int rr = 0; rr < 32; rr += 8) {
        int n = nb + ty + rr;
        int k = kb + tx;
        float v = t[tx][ty + rr];
        out[pk_off(n >> 7, k >> 4, n & 127, (k >> 2) & 3, k & 3)] = v;
    }
}

// ================= TMA-bulk TF32 tensor-core GEMM =================
// C(M,N) = A @ B^T, operands pre-packed as [blk128][kt][128 x 16 tf32, swizzled 8KB].
// 256 thr, tile 128x128, BK=16, warp tile 64x32, 4-stage cp.async.bulk + mbarrier ring.
#define TILE_B      8192u
#define STG_B       16384u
#define NSTG        4
#define GEMM_SMEM   (1024 + NSTG * (int)STG_B)   // 66560

__device__ __forceinline__ uint32_t smem_u32(const void* p) {
    uint32_t a;
    asm("{ .reg .u64 tmp; cvta.to.shared.u64 tmp, %1; cvt.u32.u64 %0, tmp; }"
        : "=r"(a) : "l"(p));
    return a;
}
#define LDSM4(r0, r1, r2, r3, addr) \
    asm volatile("ldmatrix.sync.aligned.m8n8.x4.shared.b16 {%0,%1,%2,%3}, [%4];\n" \
                 : "=r"(r0), "=r"(r1), "=r"(r2), "=r"(r3) : "r"(addr))
#define EXPECT_TX(bar, n) \
    asm volatile("mbarrier.arrive.expect_tx.shared.b64 _, [%0], %1;" \
                 :: "r"(bar), "r"(n) : "memory")
#define BULK8K(dst, src, bar) \
    asm volatile("cp.async.bulk.shared::cluster.global.mbarrier::complete_tx::bytes " \
                 "[%0], [%1], %2, [%3];" \
                 :: "r"(dst), "l"(src), "r"(TILE_B), "r"(bar) : "memory")
#define MBAR_WAIT(bar, par) do {                                                  \
    asm volatile("{\n\t.reg .pred P1;\n\t"                                        \
        "WL%=:\n\t"                                                               \
        "mbarrier.try_wait.parity.acquire.cta.shared::cta.b64 P1, [%0], %1, 0x989680;\n\t" \
        "@P1 bra.uni WD%=;\n\t"                                                   \
        "bra.uni WL%=;\n\t"                                                       \
        "WD%=:\n\t}"                                                              \
        :: "r"(bar), "r"(par) : "memory"); } while (0)

__global__ void __launch_bounds__(256, 2)
tma_gemm(const float* __restrict__ Ap, const float* __restrict__ Bp,
         const float* __restrict__ bias, float* __restrict__ C, int N)
{
    extern __shared__ __align__(16) char smem[];
    const uint32_t sb = smem_u32(smem);

    const int tid  = threadIdx.x;
    const int bx   = blockIdx.x;   // N 128-block
    const int by   = blockIdx.y;   // M 128-block
    const int warp = tid >> 5;
    const int lane = tid & 31;
    const int g    = lane >> 2;
    const int t    = lane & 3;
    const int wm   = (warp & 1) * 64;
    const int wn   = (warp >> 1) * 32;

    if (tid == 0) {
        #pragma unroll
        for (int s = 0; s < NSTG; s++) {
            asm volatile("mbarrier.init.shared.b64 [%0], %1;"
                         :: "r"(sb + s * 8), "r"(1u) : "memory");
        }
    }
    __syncthreads();

    const float* Asrc = Ap + (size_t)by * (128 * DMODEL);   // [by][kt] tiles
    const float* Bsrc = Bp + (size_t)bx * (128 * DMODEL);

    if (tid == 0) {
        #pragma unroll
        for (int st = 0; st < NSTG - 1; st++) {
            uint32_t bar = sb + st * 8;
            uint32_t dst = sb + 1024u + (uint32_t)st * STG_B;
            EXPECT_TX(bar, 2 * TILE_B);
            BULK8K(dst,          Asrc + (size_t)st * 2048, bar);
            BULK8K(dst + TILE_B, Bsrc + (size_t)st * 2048, bar);
        }
    }

    // ldmatrix lane decomposition
    const int aRowL = lane & 15;
    const int aSegL = lane >> 4;                       // 0/1
    const int bRowL = (lane & 7) | ((lane & 16) >> 1);
    const int bSegL = (lane & 8) >> 3;                 // 0/1

    float c[16][4];
    #pragma unroll
    for (int i = 0; i < 16; i++)
        #pragma unroll
        for (int j = 0; j < 4; j++) c[i][j] = 0.f;

    for (int kt = 0; kt < NKT; kt++) {
        MBAR_WAIT(sb + (kt & 3) * 8, (kt >> 2) & 1);
        __syncthreads();

        if (tid == 0 && kt + 3 < NKT) {
            const int slot = (kt + 3) & 3;
            uint32_t bar = sb + slot * 8;
            uint32_t dst = sb + 1024u + (uint32_t)slot * STG_B;
            EXPECT_TX(bar, 2 * TILE_B);
            BULK8K(dst,          Asrc + (size_t)(kt + 3) * 2048, bar);
            BULK8K(dst + TILE_B, Bsrc + (size_t)(kt + 3) * 2048, bar);
        }

        const uint32_t sA = sb + 1024u + (uint32_t)(kt & 3) * STG_B;
        const uint32_t sBm = sA + TILE_B;

        #pragma unroll
        for (int ks = 0; ks < 2; ks++) {
            unsigned a[4][4], b[4][2];
            #pragma unroll
            for (int i = 0; i < 4; i++) {
                int row = wm + i * 16 + aRowL;
                int cseg = ks * 2 + aSegL;
                unsigned addr = sA +
                    (unsigned)(row * 64 + (((cseg + ((row >> 1) & 3)) & 3) << 4));
                LDSM4(a[i][0], a[i][1], a[i][2], a[i][3], addr);
            }
            #pragma unroll
            for (int jp = 0; jp < 2; jp++) {
                int row = wn + jp * 16 + bRowL;
                int cseg = ks * 2 + bSegL;
                unsigned addr = sBm +
                    (unsigned)(row * 64 + (((cseg + ((row >> 1) & 3)) & 3) << 4));
                LDSM4(b[2*jp][0], b[2*jp][1], b[2*jp+1][0], b[2*jp+1][1], addr);
            }
            #pragma unroll
            for (int i = 0; i < 4; i++)
                #pragma unroll
                for (int j = 0; j < 4; j++) {
                    asm volatile(
                        "mma.sync.aligned.m16n8k8.row.col.f32.tf32.tf32.f32 "
                        "{%0,%1,%2,%3}, {%4,%5,%6,%7}, {%8,%9}, {%0,%1,%2,%3};\n"
                        : "+f"(c[i*4+j][0]), "+f"(c[i*4+j][1]),
                          "+f"(c[i*4+j][2]), "+f"(c[i*4+j][3])
                        : "r"(a[i][0]), "r"(a[i][1]), "r"(a[i][2]), "r"(a[i][3]),
                          "r"(b[j][0]), "r"(b[j][1]));
                }
        }
    }

    // ---- epilogue ----
    #pragma unroll
    for (int i = 0; i < 4; i++) {
        #pragma unroll
        for (int j = 0; j < 4; j++) {
            const int row = by * 128 + wm + i * 16 + g;
            const int col = bx * 128 + wn + j * 8 + 2 * t;
            if (col < N) {
                float b0 = 0.f, b1 = 0.f;
                if (bias) { b0 = __ldg(&bias[col]); b1 = __ldg(&bias[col + 1]); }
                float2 v0 = make_float2(c[i*4+j][0] + b0, c[i*4+j][1] + b1);
                float2 v1 = make_float2(c[i*4+j][2] + b0, c[i*4+j][3] + b1);
                *(float2*)&C[(size_t)row * N + col]       = v0;
                *(float2*)&C[(size_t)(row + 8) * N + col] = v1;
            }
        }
    }
}

// ---------------- causal depthwise conv1d (K=4) + SiLU ----------------
__global__ void conv_silu_kernel(const float* __restrict__ conv_w,
                                 const float* __restrict__ conv_b)
{
    int idx = blockIdx.x * blockDim.x + threadIdx.x;
    if (idx >= BL * CONVDIM) return;
    int c = idx % CONVDIM;
    int m = idx / CONVDIM;
    int l = m % LSEQ;

    float acc = conv_b[c];
    #pragma unroll
    for (int k = 0; k < KCONV; k++) {
        int lk = l - (KCONV - 1) + k;
        if (lk >= 0) {
            acc += g_proj[(size_t)(m - (KCONV - 1) + k) * PROJW + DMODEL + c]
                   * conv_w[c * KCONV + k];
        }
    }
    acc = acc / (1.f + expf(-acc));
    g_conv[(size_t)m * CONVDIM + c] = acc;
}

// ---------------- dt / dA ----------------
__global__ void dt_kernel(const float* __restrict__ A_log,
                          const float* __restrict__ dt_bias)
{
    int idx = blockIdx.x * blockDim.x + threadIdx.x;
    if (idx >= BL * HEADS) return;
    int h = idx % HEADS;
    int m = idx / HEADS;
    int b = m / LSEQ;
    int l = m % LSEQ;

    float raw = g_proj[(size_t)m * PROJW + DMODEL + CONVDIM + h] + dt_bias[h];
    float dt  = (raw > 20.f) ? raw : log1pf(expf(raw));
    float dA  = expf(dt * (-expf(A_log[h])));
    size_t o  = ((size_t)(b * HEADS + h)) * LSEQ + l;
    g_dt[o] = dt;
    g_dA[o] = dA;
}

// ---------------- selective scan ----------------
#define SD 8

__global__ __launch_bounds__(128, 1)
void scan_kernel(const float* __restrict__ D_param)
{
    const int h   = blockIdx.x;
    const int b   = blockIdx.y;
    const int tid = threadIdx.x;

    __shared__ float s_dt[LSEQ];
    __shared__ float s_dA[LSEQ];
    __shared__ __align__(16) float s_pipe[SD][128];

    {
        const float* dtp = g_dt + ((size_t)(b * HEADS + h)) * LSEQ;
        const float* dAp = g_dA + ((size_t)(b * HEADS + h)) * LSEQ;
        for (int i = tid; i < LSEQ; i += 128) {
            s_dt[i] = dtp[i];
            s_dA[i] = dAp[i];
        }
    }

    const int p    = tid >> 1;
    const int half = tid & 1;
    const float Dh = D_param[h];

    unsigned long long hs[8];
    #pragma unroll
    for (int i = 0; i < 8; i++) hs[i] = 0ull;

    const bool loader = (tid < 32);
    size_t srcoff = 0; int dstoff = 0;
    if (loader) {
        if (tid < 16) { srcoff = (size_t)h * HDIM + tid * 4; dstoff = tid * 4; }
        else          { srcoff = (size_t)DMODEL + (tid - 16) * 4; dstoff = 64 + (tid - 16) * 4; }
    }
    const float* convb = g_conv + (size_t)b * LSEQ * CONVDIM;
    unsigned sbase = (unsigned)__cvta_generic_to_shared(&s_pipe[0][0]);

    #pragma unroll
    for (int tt = 0; tt < SD - 1; tt++) {
        if (loader) {
            const float* src = convb + (size_t)tt * CONVDIM + srcoff;
            unsigned dst = sbase + (unsigned)((tt & (SD - 1)) * 128 + dstoff) * 4u;
            asm volatile("cp.async.ca.shared.global [%0], [%1], 16;\n"
                         :: "r"(dst), "l"(src));
        }
        asm volatile("cp.async.commit_group;\n" ::: "memory");
    }

    float* yout = g_y + (size_t)b * LSEQ * DMODEL + h * HDIM + p;

    for (int tc = 0; tc < LSEQ; tc++) {
        asm volatile("cp.async.wait_group 6;\n" ::: "memory");
        __syncthreads();

        const int nt = tc + SD - 1;
        if (loader && nt < LSEQ) {
            const float* src = convb + (size_t)nt * CONVDIM + srcoff;
            unsigned dst = sbase + (unsigned)((nt & (SD - 1)) * 128 + dstoff) * 4u;
            asm volatile("cp.async.ca.shared.global [%0], [%1], 16;\n"
                         :: "r"(dst), "l"(src));
        }
        asm volatile("cp.async.commit_group;\n" ::: "memory");

        const float* sl = s_pipe[tc & (SD - 1)];
        float xv  = sl[p];
        float dtv = s_dt[tc];
        float dav = s_dA[tc];
        float coef = dtv * xv;
        unsigned long long c2 = pack2(coef, coef);
        unsigned long long d2 = pack2(dav, dav);
        const unsigned long long* B2 = (const unsigned long long*)(sl + 64) + half * 8;
        const unsigned long long* C2 = (const unsigned long long*)(sl + 96) + half * 8;

        unsigned long long acc0 = 0ull, acc1 = 0ull;
        #pragma unroll
        for (int i = 0; i < 8; i++) {
            unsigned long long u = mul2(c2, B2[i]);
            hs[i] = fma2v(d2, hs[i], u);
            if (i & 1) acc1 = fma2v(hs[i], C2[i], acc1);
            else       acc0 = fma2v(hs[i], C2[i], acc0);
        }
        unsigned long long s = add2(acc0, acc1);
        float mine = lo32(s) + hi32(s);
        float other = __shfl_xor_sync(0xffffffffu, mine, 1);
        if (half == 0) {
            yout[(size_t)tc * DMODEL] = mine + other + Dh * xv;
        }
    }
}

// ---------------- gated RMSNorm -> packed tf32 y ----------------
__global__ void __launch_bounds__(256)
rmsnorm_kernel(const float* __restrict__ norm_w)
{
    const int m   = blockIdx.x;
    const int tid = threadIdx.x;
    const float* yrow = g_y    + (size_t)m * DMODEL;
    const float* grow = g_proj + (size_t)m * PROJW;   // gate = proj[:, 0:2048]

    float v[8];
    float ss = 0.f;
    #pragma unroll
    for (int k = 0; k < 8; k++) {
        int j = tid + k * 256;
        float gt  = grow[j];
        float val = yrow[j] * (gt / (1.f + expf(-gt)));
        v[k] = val;
        ss += val * val;
    }
    #pragma unroll
    for (int o = 16; o > 0; o >>= 1) ss += __shfl_xor_sync(0xffffffffu, ss, o);

    __shared__ float sred[8];
    if ((tid & 31) == 0) sred[tid >> 5] = ss;
    __syncthreads();
    float tot = sred[0] + sred[1] + sred[2] + sred[3]
              + sred[4] + sred[5] + sred[6] + sred[7];
    float scale = rsqrtf(tot * (1.f / DMODEL) + 1e-6f);

    const int mb = m >> 7, r = m & 127;
    #pragma unroll
    for (int k = 0; k < 8; k++) {
        int j = tid + k * 256;
        float val = tf32r(v[k] * scale * norm_w[j]);
        g_ya[pk_off(mb, j >> 4, r, (j >> 2) & 3, j & 3)] = val;
    }
}

// ---------------- launch ----------------
extern "C" void kernel_launch(void* const* d_in, const int* in_sizes, int n_in,
                              void* d_out, int out_size)
{
    const float* x       = (const float*)d_in[0];
    const float* W_in    = (const float*)d_in[1];
    const float* b_in    = (const float*)d_in[2];
    const float* conv_w  = (const float*)d_in[3];
    const float* conv_b  = (const float*)d_in[4];
    const float* A_log   = (const float*)d_in[5];
    const float* dt_bias = (const float*)d_in[6];
    const float* D_par   = (const float*)d_in[7];
    const float* norm_w  = (const float*)d_in[8];
    const float* W_out   = (const float*)d_in[9];
    float* out = (float*)d_out;

    float *proj, *xa, *ya, *wa, *wb;
    cudaGetSymbolAddress((void**)&proj, g_proj);
    cudaGetSymbolAddress((void**)&xa,   g_xa);
    cudaGetSymbolAddress((void**)&ya,   g_ya);
    cudaGetSymbolAddress((void**)&wa,   g_wa);
    cudaGetSymbolAddress((void**)&wb,   g_wb);

    cudaFuncSetAttribute(tma_gemm, cudaFuncAttributeMaxDynamicSharedMemorySize,
                         GEMM_SMEM);

    // 0) pack x (tf32); transpose+pack W_in, W_out
    {
        int nseg = BL * DMODEL / 4;
        round_pack_kernel<<<(nseg + 255) / 256, 256>>>(x, xa);
        dim3 blk(32, 8);
        transpose_pack_kernel<<<dim3(PROJPAD / 32, DMODEL / 32), blk>>>(W_in, wa, PROJW);
        transpose_pack_kernel<<<dim3(DMODEL / 32, DMODEL / 32), blk>>>(W_out, wb, DMODEL);
    }
    // 1) proj = x @ W_in + b_in
    {
        dim3 grid(PROJPAD / 128, BL / 128);
        tma_gemm<<<grid, 256, GEMM_SMEM>>>(xa, wa, b_in, proj, PROJW);
    }
    // 2) conv + SiLU
    {
        int total = BL * CONVDIM;
        conv_silu_kernel<<<(total + 255) / 256, 256>>>(conv_w, conv_b);
    }
    // 3) dt / dA
    {
        int total = BL * HEADS;
        dt_kernel<<<(total + 255) / 256, 256>>>(A_log, dt_bias);
    }
    // 4) selective scan
    scan_kernel<<<dim3(HEADS, BATCH), 128>>>(D_par);
    // 5) gated RMSNorm (packs y as tf32)
    rmsnorm_kernel<<<BL, 256>>>(norm_w);
    // 6) out = y @ W_out
    {
        dim3 grid(DMODEL / 128, BL / 128);
        tma_gemm<<<grid, 256, GEMM_SMEM>>>(ya, wb, nullptr, out, DMODEL);
    }
}

// round 14
// speedup vs baseline: 1.3878x; 1.0049x over previous
#include <cuda_runtime.h>
#include <cstdint>
#include <cstddef>

// ---------------- problem constants ----------------
#define HEADS   32
#define HDIM    64
#define NSTATE  32
#define KCONV   4
#define DMODEL  2048
#define CONVDIM 2112
#define PROJW   4192
#define BATCH   4
#define LSEQ    2048
#define BL      (BATCH * LSEQ)   // 8192
#define PROJPAD 4352             // padded N for GEMM1 (34 * 128)
#define NKT     128              // K / 16 k-tiles
#define NKT2    64               // K / 32 stage-blocks

// ---------------- scratch (device globals; no runtime alloc) ----------------
__device__ float g_proj[(size_t)BL * PROJW];       // 137 MB
__device__ float g_conv[(size_t)BL * CONVDIM];     // 69 MB
__device__ float g_dt  [(size_t)BATCH * HEADS * LSEQ];
__device__ float g_dA  [(size_t)BATCH * HEADS * LSEQ];
__device__ float g_y   [(size_t)BL * DMODEL];      // scan output (fp32 rows)
__device__ float g_xa  [(size_t)BL * DMODEL];      // packed tf32 x   [mb][kt][tile]
__device__ float g_ya  [(size_t)BL * DMODEL];      // packed tf32 y   [mb][kt][tile]
__device__ float g_wa  [(size_t)PROJPAD * DMODEL]; // packed tf32 W_in^T
__device__ float g_wb  [(size_t)DMODEL * DMODEL];  // packed tf32 W_out^T

// ---------------- packed fp32x2 helpers (scan) ----------------
__device__ __forceinline__ unsigned long long pack2(float lo, float hi) {
    unsigned long long r;
    asm("mov.b64 %0, {%1, %2};" : "=l"(r) : "f"(lo), "f"(hi));
    return r;
}
__device__ __forceinline__ unsigned long long mul2(unsigned long long a, unsigned long long b) {
    unsigned long long r;
    asm("mul.rn.f32x2 %0, %1, %2;" : "=l"(r) : "l"(a), "l"(b));
    return r;
}
__device__ __forceinline__ unsigned long long fma2v(unsigned long long a, unsigned long long b,
                                                    unsigned long long c) {
    unsigned long long r;
    asm("fma.rn.f32x2 %0, %1, %2, %3;" : "=l"(r) : "l"(a), "l"(b), "l"(c));
    return r;
}
__device__ __forceinline__ unsigned long long add2(unsigned long long a, unsigned long long b) {
    unsigned long long r;
    asm("add.rn.f32x2 %0, %1, %2;" : "=l"(r) : "l"(a), "l"(b));
    return r;
}
__device__ __forceinline__ float lo32(unsigned long long v) {
    return __uint_as_float((unsigned)(v & 0xffffffffull));
}
__device__ __forceinline__ float hi32(unsigned long long v) {
    return __uint_as_float((unsigned)(v >> 32));
}
__device__ __forceinline__ float tf32r(float x) {
    unsigned r;
    asm("cvt.rna.tf32.f32 %0, %1;" : "=r"(r) : "f"(x));
    return __uint_as_float(r);
}

// packed-tile float offset: r = row in 128-block, kt = k-tile, s = 16B seg, e = elem
__device__ __forceinline__ size_t pk_off(int blk, int kt, int r, int s, int e) {
    return (((size_t)blk * NKT + kt) << 11) + (size_t)r * 16 +
           (size_t)(((s + (r >> 1)) & 3) << 2) + e;
}

// ---------------- x -> packed tf32 ----------------
__global__ void round_pack_kernel(const float* __restrict__ in, float* __restrict__ out)
{
    int i = blockIdx.x * blockDim.x + threadIdx.x;   // one 16B seg
    if (i >= BL * DMODEL / 4) return;
    int m  = i >> 9;
    int sj = i & 511;
    int kt = sj >> 2, s = sj & 3;
    int mb = m >> 7,  r = m & 127;
    float4 v = ((const float4*)in)[i];
    v.x = tf32r(v.x); v.y = tf32r(v.y); v.z = tf32r(v.z); v.w = tf32r(v.w);
    size_t d = pk_off(mb, kt, r, s, 0);
    *(float4*)(out + d) = v;
}

// ---------------- W[k][n] -> packed tf32 of W^T (n-major), rows padded 0 ----------------
__global__ void transpose_pack_kernel(const float* __restrict__ in, float* __restrict__ out,
                                      int N)
{
    __shared__ float t[32][33];
    const int nb = blockIdx.x * 32;
    const int kb = blockIdx.y * 32;
    const int tx = threadIdx.x;
    const int ty = threadIdx.y;     // 0..7
    #pragma unroll
    for (int rr = 0; rr < 32; rr += 8) {
        int n = nb + tx;
        t[ty + rr][tx] = (n < N) ? tf32r(in[(size_t)(kb + ty + rr) * N + n]) : 0.f;
    }
    __syncthreads();
    #pragma unroll
    for (int rr = 0; rr < 32; rr += 8) {
        int n = nb + ty + rr;
        int k = kb + tx;
        float v = t[tx][ty + rr];
        out[pk_off(n >> 7, k >> 4, n & 127, (k >> 2) & 3, k & 3)] = v;
    }
}

// ================= TMA-bulk TF32 tensor-core GEMM =================
// C(M,N) = A @ B^T, operands pre-packed as [blk128][kt][128 x 16 tf32, swizzled 8KB].
// 256 thr, tile 128x128, BK=32 per stage (two k-tiles = one contiguous 16KB bulk),
// warp tile 64x32, 3-stage cp.async.bulk + mbarrier ring, 2 CTAs/SM.
#define OPER_B      16384u                       // 16 KB per operand per stage
#define STG_B       32768u
#define NSTG        3
#define GEMM_SMEM   (1024 + NSTG * (int)STG_B)   // 99328

__device__ __forceinline__ uint32_t smem_u32(const void* p) {
    uint32_t a;
    asm("{ .reg .u64 tmp; cvta.to.shared.u64 tmp, %1; cvt.u32.u64 %0, tmp; }"
        : "=r"(a) : "l"(p));
    return a;
}
#define LDSM4(r0, r1, r2, r3, addr) \
    asm volatile("ldmatrix.sync.aligned.m8n8.x4.shared.b16 {%0,%1,%2,%3}, [%4];\n" \
                 : "=r"(r0), "=r"(r1), "=r"(r2), "=r"(r3) : "r"(addr))
#define EXPECT_TX(bar, n) \
    asm volatile("mbarrier.arrive.expect_tx.shared.b64 _, [%0], %1;" \
                 :: "r"(bar), "r"(n) : "memory")
#define BULK16K(dst, src, bar) \
    asm volatile("cp.async.bulk.shared::cluster.global.mbarrier::complete_tx::bytes " \
                 "[%0], [%1], %2, [%3];" \
                 :: "r"(dst), "l"(src), "r"(OPER_B), "r"(bar) : "memory")
#define MBAR_WAIT(bar, par) do {                                                  \
    asm volatile("{\n\t.reg .pred P1;\n\t"                                        \
        "WL%=:\n\t"                                                               \
        "mbarrier.try_wait.parity.acquire.cta.shared::cta.b64 P1, [%0], %1, 0x989680;\n\t" \
        "@P1 bra.uni WD%=;\n\t"                                                   \
        "bra.uni WL%=;\n\t"                                                       \
        "WD%=:\n\t}"                                                              \
        :: "r"(bar), "r"(par) : "memory"); } while (0)

__global__ void __launch_bounds__(256, 2)
tma_gemm(const float* __restrict__ Ap, const float* __restrict__ Bp,
         const float* __restrict__ bias, float* __restrict__ C, int N)
{
    extern __shared__ __align__(16) char smem[];
    const uint32_t sb = smem_u32(smem);

    const int tid  = threadIdx.x;
    const int bx   = blockIdx.x;   // N 128-block
    const int by   = blockIdx.y;   // M 128-block
    const int warp = tid >> 5;
    const int lane = tid & 31;
    const int g    = lane >> 2;
    const int t    = lane & 3;
    const int wm   = (warp & 1) * 64;
    const int wn   = (warp >> 1) * 32;

    if (tid == 0) {
        #pragma unroll
        for (int s = 0; s < NSTG; s++) {
            asm volatile("mbarrier.init.shared.b64 [%0], %1;"
                         :: "r"(sb + s * 8), "r"(1u) : "memory");
        }
    }
    __syncthreads();

    const float* Asrc = Ap + (size_t)by * (128 * DMODEL);
    const float* Bsrc = Bp + (size_t)bx * (128 * DMODEL);

    if (tid == 0) {
        #pragma unroll
        for (int st = 0; st < NSTG - 1; st++) {
            uint32_t bar = sb + st * 8;
            uint32_t dst = sb + 1024u + (uint32_t)st * STG_B;
            EXPECT_TX(bar, 2 * OPER_B);
            BULK16K(dst,          Asrc + (size_t)st * 4096, bar);
            BULK16K(dst + OPER_B, Bsrc + (size_t)st * 4096, bar);
        }
    }

    // ldmatrix lane decomposition
    const int aRowL = lane & 15;
    const int aSegL = lane >> 4;
    const int bRowL = (lane & 7) | ((lane & 16) >> 1);
    const int bSegL = (lane & 8) >> 3;

    float c[16][4];
    #pragma unroll
    for (int i = 0; i < 16; i++)
        #pragma unroll
        for (int j = 0; j < 4; j++) c[i][j] = 0.f;

    for (int kb = 0; kb < NKT2; kb++) {
        const int slot = kb % NSTG;
        MBAR_WAIT(sb + slot * 8, (kb / NSTG) & 1);
        __syncthreads();

        if (tid == 0 && kb + 2 < NKT2) {
            const int ns = (kb + 2) % NSTG;
            uint32_t bar = sb + ns * 8;
            uint32_t dst = sb + 1024u + (uint32_t)ns * STG_B;
            EXPECT_TX(bar, 2 * OPER_B);
            BULK16K(dst,          Asrc + (size_t)(kb + 2) * 4096, bar);
            BULK16K(dst + OPER_B, Bsrc + (size_t)(kb + 2) * 4096, bar);
        }

        const uint32_t sA = sb + 1024u + (uint32_t)slot * STG_B;
        const uint32_t sBm = sA + OPER_B;

        #pragma unroll
        for (int ks = 0; ks < 4; ks++) {
            const unsigned toff = (unsigned)(ks >> 1) * 8192u;
            unsigned a[4][4], b[4][2];
            #pragma unroll
            for (int i = 0; i < 4; i++) {
                int row = wm + i * 16 + aRowL;
                int cseg = (ks & 1) * 2 + aSegL;
                unsigned addr = sA + toff +
                    (unsigned)(row * 64 + (((cseg + ((row >> 1) & 3)) & 3) << 4));
                LDSM4(a[i][0], a[i][1], a[i][2], a[i][3], addr);
            }
            #pragma unroll
            for (int jp = 0; jp < 2; jp++) {
                int row = wn + jp * 16 + bRowL;
                int cseg = (ks & 1) * 2 + bSegL;
                unsigned addr = sBm + toff +
                    (unsigned)(row * 64 + (((cseg + ((row >> 1) & 3)) & 3) << 4));
                LDSM4(b[2*jp][0], b[2*jp][1], b[2*jp+1][0], b[2*jp+1][1], addr);
            }
            #pragma unroll
            for (int i = 0; i < 4; i++)
                #pragma unroll
                for (int j = 0; j < 4; j++) {
                    asm volatile(
                        "mma.sync.aligned.m16n8k8.row.col.f32.tf32.tf32.f32 "
                        "{%0,%1,%2,%3}, {%4,%5,%6,%7}, {%8,%9}, {%0,%1,%2,%3};\n"
                        : "+f"(c[i*4+j][0]), "+f"(c[i*4+j][1]),
                          "+f"(c[i*4+j][2]), "+f"(c[i*4+j][3])
                        : "r"(a[i][0]), "r"(a[i][1]), "r"(a[i][2]), "r"(a[i][3]),
                          "r"(b[j][0]), "r"(b[j][1]));
                }
        }
    }

    // ---- epilogue ----
    #pragma unroll
    for (int i = 0; i < 4; i++) {
        #pragma unroll
        for (int j = 0; j < 4; j++) {
            const int row = by * 128 + wm + i * 16 + g;
            const int col = bx * 128 + wn + j * 8 + 2 * t;
            if (col < N) {
                float b0 = 0.f, b1 = 0.f;
                if (bias) { b0 = __ldg(&bias[col]); b1 = __ldg(&bias[col + 1]); }
                float2 v0 = make_float2(c[i*4+j][0] + b0, c[i*4+j][1] + b1);
                float2 v1 = make_float2(c[i*4+j][2] + b0, c[i*4+j][3] + b1);
                *(float2*)&C[(size_t)row * N + col]       = v0;
                *(float2*)&C[(size_t)(row + 8) * N + col] = v1;
            }
        }
    }
}

// ---------------- causal depthwise conv1d (K=4) + SiLU ----------------
__global__ void conv_silu_kernel(const float* __restrict__ conv_w,
                                 const float* __restrict__ conv_b)
{
    int idx = blockIdx.x * blockDim.x + threadIdx.x;
    if (idx >= BL * CONVDIM) return;
    int c = idx % CONVDIM;
    int m = idx / CONVDIM;
    int l = m % LSEQ;

    float acc = conv_b[c];
    #pragma unroll
    for (int k = 0; k < KCONV; k++) {
        int lk = l - (KCONV - 1) + k;
        if (lk >= 0) {
            acc += g_proj[(size_t)(m - (KCONV - 1) + k) * PROJW + DMODEL + c]
                   * conv_w[c * KCONV + k];
        }
    }
    acc = acc / (1.f + expf(-acc));
    g_conv[(size_t)m * CONVDIM + c] = acc;
}

// ---------------- dt / dA ----------------
__global__ void dt_kernel(const float* __restrict__ A_log,
                          const float* __restrict__ dt_bias)
{
    int idx = blockIdx.x * blockDim.x + threadIdx.x;
    if (idx >= BL * HEADS) return;
    int h = idx % HEADS;
    int m = idx / HEADS;
    int b = m / LSEQ;
    int l = m % LSEQ;

    float raw = g_proj[(size_t)m * PROJW + DMODEL + CONVDIM + h] + dt_bias[h];
    float dt  = (raw > 20.f) ? raw : log1pf(expf(raw));
    float dA  = expf(dt * (-expf(A_log[h])));
    size_t o  = ((size_t)(b * HEADS + h)) * LSEQ + l;
    g_dt[o] = dt;
    g_dA[o] = dA;
}

// ---------------- selective scan ----------------
#define SD 8

__global__ __launch_bounds__(128, 1)
void scan_kernel(const float* __restrict__ D_param)
{
    const int h   = blockIdx.x;
    const int b   = blockIdx.y;
    const int tid = threadIdx.x;

    __shared__ float s_dt[LSEQ];
    __shared__ float s_dA[LSEQ];
    __shared__ __align__(16) float s_pipe[SD][128];

    {
        const float* dtp = g_dt + ((size_t)(b * HEADS + h)) * LSEQ;
        const float* dAp = g_dA + ((size_t)(b * HEADS + h)) * LSEQ;
        for (int i = tid; i < LSEQ; i += 128) {
            s_dt[i] = dtp[i];
            s_dA[i] = dAp[i];
        }
    }

    const int p    = tid >> 1;
    const int half = tid & 1;
    const float Dh = D_param[h];

    unsigned long long hs[8];
    #pragma unroll
    for (int i = 0; i < 8; i++) hs[i] = 0ull;

    const bool loader = (tid < 32);
    size_t srcoff = 0; int dstoff = 0;
    if (loader) {
        if (tid < 16) { srcoff = (size_t)h * HDIM + tid * 4; dstoff = tid * 4; }
        else          { srcoff = (size_t)DMODEL + (tid - 16) * 4; dstoff = 64 + (tid - 16) * 4; }
    }
    const float* convb = g_conv + (size_t)b * LSEQ * CONVDIM;
    unsigned sbase = (unsigned)__cvta_generic_to_shared(&s_pipe[0][0]);

    #pragma unroll
    for (int tt = 0; tt < SD - 1; tt++) {
        if (loader) {
            const float* src = convb + (size_t)tt * CONVDIM + srcoff;
            unsigned dst = sbase + (unsigned)((tt & (SD - 1)) * 128 + dstoff) * 4u;
            asm volatile("cp.async.ca.shared.global [%0], [%1], 16;\n"
                         :: "r"(dst), "l"(src));
        }
        asm volatile("cp.async.commit_group;\n" ::: "memory");
    }

    float* yout = g_y + (size_t)b * LSEQ * DMODEL + h * HDIM + p;

    for (int tc = 0; tc < LSEQ; tc++) {
        asm volatile("cp.async.wait_group 6;\n" ::: "memory");
        __syncthreads();

        const int nt = tc + SD - 1;
        if (loader && nt < LSEQ) {
            const float* src = convb + (size_t)nt * CONVDIM + srcoff;
            unsigned dst = sbase + (unsigned)((nt & (SD - 1)) * 128 + dstoff) * 4u;
            asm volatile("cp.async.ca.shared.global [%0], [%1], 16;\n"
                         :: "r"(dst), "l"(src));
        }
        asm volatile("cp.async.commit_group;\n" ::: "memory");

        const float* sl = s_pipe[tc & (SD - 1)];
        float xv  = sl[p];
        float dtv = s_dt[tc];
        float dav = s_dA[tc];
        float coef = dtv * xv;
        unsigned long long c2 = pack2(coef, coef);
        unsigned long long d2 = pack2(dav, dav);
        const unsigned long long* B2 = (const unsigned long long*)(sl + 64) + half * 8;
        const unsigned long long* C2 = (const unsigned long long*)(sl + 96) + half * 8;

        unsigned long long acc0 = 0ull, acc1 = 0ull;
        #pragma unroll
        for (int i = 0; i < 8; i++) {
            unsigned long long u = mul2(c2, B2[i]);
            hs[i] = fma2v(d2, hs[i], u);
            if (i & 1) acc1 = fma2v(hs[i], C2[i], acc1);
            else       acc0 = fma2v(hs[i], C2[i], acc0);
        }
        unsigned long long s = add2(acc0, acc1);
        float mine = lo32(s) + hi32(s);
        float other = __shfl_xor_sync(0xffffffffu, mine, 1);
        if (half == 0) {
            yout[(size_t)tc * DMODEL] = mine + other + Dh * xv;
        }
    }
}

// ---------------- gated RMSNorm -> packed tf32 y ----------------
__global__ void __launch_bounds__(256)
rmsnorm_kernel(const float* __restrict__ norm_w)
{
    const int m   = blockIdx.x;
    const int tid = threadIdx.x;
    const float* yrow = g_y    + (size_t)m * DMODEL;
    const float* grow = g_proj + (size_t)m * PROJW;   // gate = proj[:, 0:2048]

    float v[8];
    float ss = 0.f;
    #pragma unroll
    for (int k = 0; k < 8; k++) {
        int j = tid + k * 256;
        float gt  = grow[j];
        float val = yrow[j] * (gt / (1.f + expf(-gt)));
        v[k] = val;
        ss += val * val;
    }
    #pragma unroll
    for (int o = 16; o > 0; o >>= 1) ss += __shfl_xor_sync(0xffffffffu, ss, o);

    __shared__ float sred[8];
    if ((tid & 31) == 0) sred[tid >> 5] = ss;
    __syncthreads();
    float tot = sred[0] + sred[1] + sred[2] + sred[3]
              + sred[4] + sred[5] + sred[6] + sred[7];
    float scale = rsqrtf(tot * (1.f / DMODEL) + 1e-6f);

    const int mb = m >> 7, r = m & 127;
    #pragma unroll
    for (int k = 0; k < 8; k++) {
        int j = tid + k * 256;
        float val = tf32r(v[k] * scale * norm_w[j]);
        g_ya[pk_off(mb, j >> 4, r, (j >> 2) & 3, j & 3)] = val;
    }
}

// ---------------- launch ----------------
extern "C" void kernel_launch(void* const* d_in, const int* in_sizes, int n_in,
                              void* d_out, int out_size)
{
    const float* x       = (const float*)d_in[0];
    const float* W_in    = (const float*)d_in[1];
    const float* b_in    = (const float*)d_in[2];
    const float* conv_w  = (const float*)d_in[3];
    const float* conv_b  = (const float*)d_in[4];
    const float* A_log   = (const float*)d_in[5];
    const float* dt_bias = (const float*)d_in[6];
    const float* D_par   = (const float*)d_in[7];
    const float* norm_w  = (const float*)d_in[8];
    const float* W_out   = (const float*)d_in[9];
    float* out = (float*)d_out;

    float *proj, *xa, *ya, *wa, *wb;
    cudaGetSymbolAddress((void**)&proj, g_proj);
    cudaGetSymbolAddress((void**)&xa,   g_xa);
    cudaGetSymbolAddress((void**)&ya,   g_ya);
    cudaGetSymbolAddress((void**)&wa,   g_wa);
    cudaGetSymbolAddress((void**)&wb,   g_wb);

    cudaFuncSetAttribute(tma_gemm, cudaFuncAttributeMaxDynamicSharedMemorySize,
                         GEMM_SMEM);

    // 0) pack x (tf32); transpose+pack W_in, W_out
    {
        int nseg = BL * DMODEL / 4;
        round_pack_kernel<<<(nseg + 255) / 256, 256>>>(x, xa);
        dim3 blk(32, 8);
        transpose_pack_kernel<<<dim3(PROJPAD / 32, DMODEL / 32), blk>>>(W_in, wa, PROJW);
        transpose_pack_kernel<<<dim3(DMODEL / 32, DMODEL / 32), blk>>>(W_out, wb, DMODEL);
    }
    // 1) proj = x @ W_in + b_in
    {
        dim3 grid(PROJPAD / 128, BL / 128);
        tma_gemm<<<grid, 256, GEMM_SMEM>>>(xa, wa, b_in, proj, PROJW);
    }
    // 2) conv + SiLU
    {
        int total = BL * CONVDIM;
        conv_silu_kernel<<<(total + 255) / 256, 256>>>(conv_w, conv_b);
    }
    // 3) dt / dA
    {
        int total = BL * HEADS;
        dt_kernel<<<(total + 255) / 256, 256>>>(A_log, dt_bias);
    }
    // 4) selective scan
    scan_kernel<<<dim3(HEADS, BATCH), 128>>>(D_par);
    // 5) gated RMSNorm (packs y as tf32)
    rmsnorm_kernel<<<BL, 256>>>(norm_w);
    // 6) out = y @ W_out
    {
        dim3 grid(DMODEL / 128, BL / 128);
        tma_gemm<<<grid, 256, GEMM_SMEM>>>(ya, wb, nullptr, out, DMODEL);
    }
}